// round 14
// baseline (speedup 1.0000x reference)
#include <cuda_runtime.h>
#include <cstdint>

#define VOCAB   32000
#define EMB     43
#define LAYERS  64
#define OUT_DIM 15

#define TPB     224          // 7 warps, 1 etile/warp -> 112 entries/CTA
#define EPB     112
#define NBLK    286          // 286*112 = 32032 >= 32000; 2 CTAs/SM

// ---- int8 inner-layer weight block (layers 0..61) ----
#define LIB     6928                  // bytes: B0 4608 | B1 2304 | scales 16
#define LIB_U   (LIB / 4)             // 1732 uints
#define N16I    (LIB / 16)            // 433 16B-chunks

// ---- bf16 split-2 tail block (layers 62,63) ----
#define NF2     54
#define HALF_B  (NF2 * 256)           // 13824
#define B_LAYER (2 * HALF_B)          // 27648
#define UPL     (B_LAYER / 4)         // 6912

// smem layout (bytes)
#define SM_W0    0
#define SM_W1    LIB                   // 6928
#define SM_H     (2 * LIB)             // 13856 : int8 h, 7 warps x 768
#define SM_T62   (SM_H + 7 * 768)      // 19232 : tail layer 62 frags (27648)
#define SM_T63   (SM_T62 + B_LAYER)    // 46880 : tail layer 63 frags
#define SM_WOUT  (SM_T63 + B_LAYER)    // 74528
#define SM_BOUT  (SM_WOUT + OUT_DIM * EMB * 4)  // 77108
#define SM_TOTAL 77184
// hb (final h, float[112*45] = 20160 B) aliases SM_T62 (free during layer 63)

typedef unsigned int uint;

__device__ float g_table[VOCAB * OUT_DIM];
__device__ uint  g_Bi[(size_t)62 * LIB_U];   // int8 frags + scales, layers 0..61
__device__ uint  g_Bf[(size_t)2 * UPL];      // bf16 split-2 frags, layers 62..63

// ---------------- helpers ----------------
__device__ __forceinline__ uint smaddr(const void* p) {
    uint a;
    asm("{ .reg .u64 t; cvta.to.shared.u64 t, %1; cvt.u32.u64 %0, t; }"
        : "=r"(a) : "l"(p));
    return a;
}
__device__ __forceinline__ void cp16(uint sa, const void* g) {
    asm volatile("cp.async.ca.shared.global [%0], [%1], 16;" :: "r"(sa), "l"(g));
}
__device__ __forceinline__ void mma_bf16(float d[4], const uint a[4], uint b0, uint b1) {
    asm volatile(
        "mma.sync.aligned.m16n8k16.row.col.f32.bf16.bf16.f32 "
        "{%0,%1,%2,%3}, {%4,%5,%6,%7}, {%8,%9}, {%0,%1,%2,%3};"
        : "+f"(d[0]), "+f"(d[1]), "+f"(d[2]), "+f"(d[3])
        : "r"(a[0]), "r"(a[1]), "r"(a[2]), "r"(a[3]), "r"(b0), "r"(b1));
}
__device__ __forceinline__ void mma_s8(int d[4], uint a0, uint a1, uint a2, uint a3,
                                       uint b0, uint b1) {
    asm volatile(
        "mma.sync.aligned.m16n8k32.row.col.s32.s8.s8.s32 "
        "{%0,%1,%2,%3}, {%4,%5,%6,%7}, {%8,%9}, {%0,%1,%2,%3};"
        : "+r"(d[0]), "+r"(d[1]), "+r"(d[2]), "+r"(d[3])
        : "r"(a0), "r"(a1), "r"(a2), "r"(a3), "r"(b0), "r"(b1));
}
__device__ __forceinline__ uint pack_h2(float hi, float lo) {
    uint d;
    asm("cvt.rn.f16x2.f32 %0, %1, %2;" : "=r"(d) : "f"(hi), "f"(lo));
    return d;
}
__device__ __forceinline__ void split_pack(float x0, float x1, uint& hi, uint& lo) {
    asm("cvt.rn.bf16x2.f32 %0, %1, %2;" : "=r"(hi) : "f"(x1), "f"(x0));
    float r0 = x0 - __uint_as_float(hi << 16);
    float r1 = x1 - __uint_as_float(hi & 0xFFFF0000u);
    asm("cvt.rn.bf16x2.f32 %0, %1, %2;" : "=r"(lo) : "f"(r1), "f"(r0));
}
__device__ __forceinline__ void unpack_h2(uint v, float& lo, float& hi) {
    asm("{ .reg .b16 l, h;\n\t mov.b32 {l, h}, %2;\n\t"
        "cvt.f32.f16 %0, l;\n\t cvt.f32.f16 %1, h; }"
        : "=f"(lo), "=f"(hi) : "r"(v));
}
__device__ __forceinline__ uint tanh2(uint x) {
    uint y;
    asm("tanh.approx.f16x2 %0, %1;" : "=r"(y) : "r"(x));
    return y;
}
__device__ __forceinline__ uint hfma2(uint a, uint b, uint c) {
    uint d;
    asm("fma.rn.f16x2 %0, %1, %2, %3;" : "=r"(d) : "r"(a), "r"(b), "r"(c));
    return d;
}
__device__ __forceinline__ uint hmul2(uint a, uint b) {
    uint d;
    asm("mul.rn.f16x2 %0, %1, %2;" : "=r"(d) : "r"(a), "r"(b));
    return d;
}
#define H05 0x38003800u

// f16x2 LSTM cell pair (i/o gates pre-halved via weight scale)
__device__ __forceinline__ uint cellpair2(uint di, uint dg, uint dq) {
    uint si = hfma2(tanh2(di), H05, H05);
    uint c  = hmul2(si, tanh2(dg));
    uint so = hfma2(tanh2(dq), H05, H05);
    return hmul2(so, tanh2(c));
}
// exact fp32 cell (tail layers)
__device__ __forceinline__ float cell_exact(float i, float g, float o) {
    float eg = __expf(-2.0f * fabsf(g));
    float ei = __expf(-i);
    float cc = copysignf(__fdividef(1.0f - eg, (1.0f + ei) * (1.0f + eg)), g);
    float ec = __expf(-2.0f * fabsf(cc));
    float eo = __expf(-o);
    return copysignf(__fdividef(1.0f - ec, (1.0f + eo) * (1.0f + ec)), cc);
}
// quantize f32 -> int8 byte (x in [-1,1] scale 127)
__device__ __forceinline__ uint q8r(float x) {
    float m = fminf(fmaxf(x * 127.0f, -127.0f), 127.0f);
    int q;
    asm("cvt.rni.s32.f32 %0, %1;" : "=r"(q) : "f"(m));
    return (uint)q & 0xFFu;
}
__device__ __forceinline__ int qclamp(float x) {
    float m = fminf(fmaxf(x, -127.0f), 127.0f);
    int q;
    asm("cvt.rni.s32.f32 %0, %1;" : "=r"(q) : "f"(m));
    return q;
}

// -------- tail frag coordinates (bf16 k16 layout) --------
__device__ __forceinline__ void frag_wval(const float* w_ih, const float* b_ih,
                                          const float* b_hh, int l, int rem,
                                          int& g_out, float& v0, float& v1) {
    int f2   = rem >> 6;
    int lane = (rem >> 1) & 31;
    int r    = rem & 1;
    int Kc = f2 % 3;
    int g  = (f2 / 3) % 3;
    int T  = f2 / 9;
    int m  = T * 8 + (lane >> 2);
    int k0 = Kc * 16 + r * 8 + (lane & 3) * 2;
    v0 = 0.0f; v1 = 0.0f; g_out = g;
    if (m < EMB) {
        int rg = m + (g == 1 ? 86 : (g == 2 ? 129 : 0));
        const float* wr = w_ih + ((size_t)l * 172 + rg) * EMB;
        float bias = b_ih[l * 172 + rg] + b_hh[l * 172 + rg];
        v0 = (k0 < EMB)     ? wr[k0]     : (k0 == EMB     ? bias : 0.0f);
        v1 = (k0 + 1 < EMB) ? wr[k0 + 1] : (k0 + 1 == EMB ? bias : 0.0f);
    }
}

// ---------------- prep ----------------
// blocks 0..61: int8 layer blocks; blocks 62..77: bf16 split-2 tail (62,63)
__global__ void prep_kernel(const float* __restrict__ w_ih,
                            const float* __restrict__ b_ih,
                            const float* __restrict__ b_hh)
{
    int b = blockIdx.x;
    if (b < 62) {
        int l = b;
        __shared__ int smax[3];
        if (threadIdx.x < 3) smax[threadIdx.x] = 0;
        __syncthreads();
        for (int idx = threadIdx.x; idx < 3 * 43 * 43; idx += blockDim.x) {
            int g = idx / 1849, rem = idx - g * 1849;
            int m = rem / 43, k = rem - m * 43;
            int rg = m + (g == 1 ? 86 : (g == 2 ? 129 : 0));
            float w = w_ih[((size_t)l * 172 + rg) * 43 + k];
            atomicMax(&smax[g], __float_as_int(fabsf(w)));
        }
        __syncthreads();
        float dw[3], inv[3];
        #pragma unroll
        for (int g = 0; g < 3; g++) {
            float gm = fmaxf(__int_as_float(smax[g]), 1e-8f);
            dw[g] = gm * (1.0f / 127.0f);
            inv[g] = 127.0f / gm;
        }
        for (int u = threadIdx.x; u < LIB_U; u += blockDim.x) {
            uint outv = 0;
            if (u < 1152) {                               // B0: k 0..31
                int f2 = u >> 6, lr = u & 63, lane = lr >> 1, r = lr & 1;
                int T = f2 / 3, g = f2 - T * 3;
                int gr = lane >> 2, qq = lane & 3;
                int m = T * 8 + gr;
                if (m < 43) {
                    int rg = m + (g == 1 ? 86 : (g == 2 ? 129 : 0));
                    const float* wr = w_ih + ((size_t)l * 172 + rg) * 43;
                    #pragma unroll
                    for (int bb = 0; bb < 4; bb++) {
                        int k = r * 16 + qq * 4 + bb;
                        int q = qclamp(wr[k] * inv[g]);
                        outv |= ((uint)q & 0xFFu) << (bb * 8);
                    }
                }
            } else if (u < 1728) {                        // B1: k 32..47
                int rem = u - 1152;
                int f2 = rem >> 5, lane = rem & 31;
                int T = f2 / 3, g = f2 - T * 3;
                int gr = lane >> 2, qq = lane & 3;
                int m = T * 8 + gr;
                if (m < 43) {
                    int rg = m + (g == 1 ? 86 : (g == 2 ? 129 : 0));
                    const float* wr = w_ih + ((size_t)l * 172 + rg) * 43;
                    float bias = b_ih[l * 172 + rg] + b_hh[l * 172 + rg];
                    int q1 = qclamp(bias * inv[g]);
                    float resid = bias - (float)q1 * dw[g];
                    int q2 = qclamp(resid * inv[g]);
                    #pragma unroll
                    for (int bb = 0; bb < 4; bb++) {
                        int k = 32 + qq * 4 + bb;
                        int q = 0;
                        if (k < 43)       q = qclamp(wr[k] * inv[g]);
                        else if (k == 43) q = q1;
                        else if (k == 44) q = q2;
                        outv |= ((uint)q & 0xFFu) << (bb * 8);
                    }
                }
            } else {                                      // scales
                int i = u - 1728;
                float s = 0.0f;
                if (i < 3) s = dw[i] * (1.0f / 127.0f) * (i == 1 ? 1.0f : 0.5f);
                outv = __float_as_uint(s);
            }
            g_Bi[(size_t)l * LIB_U + u] = outv;
        }
    } else {
        int bb = b - 62;
        int li = bb >> 3;                      // 0,1 -> layers 62,63
        int u0 = (bb & 7) * (UPL / 8);
        for (int u = u0 + threadIdx.x; u < u0 + UPL / 8; u += blockDim.x) {
            int hl  = (u >= UPL / 2);
            int rem = u - hl * (UPL / 2);
            int g; float v0, v1;
            frag_wval(w_ih, b_ih, b_hh, 62 + li, rem, g, v0, v1);
            uint hi;
            asm("cvt.rn.bf16x2.f32 %0, %1, %2;" : "=r"(hi) : "f"(v1), "f"(v0));
            uint outv = hi;
            if (hl) {
                float r0 = v0 - __uint_as_float(hi << 16);
                float r1 = v1 - __uint_as_float(hi & 0xFFFF0000u);
                asm("cvt.rn.bf16x2.f32 %0, %1, %2;" : "=r"(outv) : "f"(r1), "f"(r0));
            }
            g_Bf[(size_t)li * UPL + u] = outv;
        }
    }
}

// ---------------- int8 layer body (layers 0..61) ----------------
template<bool OUTSPLIT>
__device__ __forceinline__ void layer_i8(
    const char* __restrict__ bsm, char* __restrict__ hsm,
    uint (&A)[6], uint (&Oh)[3][4], uint (&Ol)[3][4], int lane)
{
    const int qq = lane & 3;
    const int gr = lane >> 2;
    const float* sc = reinterpret_cast<const float*>(bsm + 6912);
    const float S0 = sc[0], S1 = sc[1], S2 = sc[2];
    #pragma unroll
    for (int T = 0; T < 6; T++) {
        int d0[4] = {0,0,0,0}, d1[4] = {0,0,0,0}, d2[4] = {0,0,0,0};
        {
            uint2 b00 = *(const uint2*)(bsm + (T*3+0)*256 + lane*8);
            uint2 b01 = *(const uint2*)(bsm + (T*3+1)*256 + lane*8);
            uint2 b02 = *(const uint2*)(bsm + (T*3+2)*256 + lane*8);
            uint  b10 = *(const uint*)(bsm + 4608 + (T*3+0)*128 + lane*4);
            uint  b11 = *(const uint*)(bsm + 4608 + (T*3+1)*128 + lane*4);
            uint  b12 = *(const uint*)(bsm + 4608 + (T*3+2)*128 + lane*4);
            mma_s8(d0, A[0], A[1], A[2], A[3], b00.x, b00.y);
            mma_s8(d1, A[0], A[1], A[2], A[3], b01.x, b01.y);
            mma_s8(d2, A[0], A[1], A[2], A[3], b02.x, b02.y);
            mma_s8(d0, A[4], A[5], 0u, 0u, b10, 0u);
            mma_s8(d1, A[4], A[5], 0u, 0u, b11, 0u);
            mma_s8(d2, A[4], A[5], 0u, 0u, b12, 0u);
        }
        uint pi0 = pack_h2((float)d0[1] * S0, (float)d0[0] * S0);
        uint pg0 = pack_h2((float)d1[1] * S1, (float)d1[0] * S1);
        uint pq0 = pack_h2((float)d2[1] * S2, (float)d2[0] * S2);
        uint pi1 = pack_h2((float)d0[3] * S0, (float)d0[2] * S0);
        uint pg1 = pack_h2((float)d1[3] * S1, (float)d1[2] * S1);
        uint pq1 = pack_h2((float)d2[3] * S2, (float)d2[2] * S2);
        uint p0 = cellpair2(pi0, pg0, pq0);   // row gr,   cols m0, m0+1
        uint p1 = cellpair2(pi1, pg1, pq1);   // row gr+8
        int m0 = T * 8 + 2 * qq;
        if (OUTSPLIT) {
            float x0, x1, y0, y1;
            unpack_h2(p0, x0, x1);
            unpack_h2(p1, y0, y1);
            if (T == 5 && qq == 1) { x1 = 1.0f; y1 = 1.0f; }   // k=43 one-col
            int Kc = T >> 1, hh = (T & 1) * 2;
            split_pack(x0, x1, Oh[Kc][hh],     Ol[Kc][hh]);
            split_pack(y0, y1, Oh[Kc][hh + 1], Ol[Kc][hh + 1]);
        } else {
            float x0, x1, y0, y1;
            unpack_h2(p0, x0, x1);
            unpack_h2(p1, y0, y1);
            uint v0 = q8r(x0) | (q8r(x1) << 8);
            uint v1 = q8r(y0) | (q8r(y1) << 8);
            if (T == 5) {
                if (qq == 1)      { v0 = (v0 & 0xFFu) | 0x7F00u; v1 = (v1 & 0xFFu) | 0x7F00u; }
                else if (qq == 2) { v0 = 0x7Fu; v1 = 0x7Fu; }    // k44=127, k45=0
                else if (qq == 3) { v0 = 0u;    v1 = 0u;    }    // k46,47
            }
            *(unsigned short*)(hsm + gr * 48 + m0)       = (unsigned short)v0;
            *(unsigned short*)(hsm + (gr + 8) * 48 + m0) = (unsigned short)v1;
        }
    }
    if (!OUTSPLIT) {
        __syncwarp();
        A[0] = *(const uint*)(hsm + gr * 48 + 4 * qq);
        A[1] = *(const uint*)(hsm + (gr + 8) * 48 + 4 * qq);
        A[2] = *(const uint*)(hsm + gr * 48 + 16 + 4 * qq);
        A[3] = *(const uint*)(hsm + (gr + 8) * 48 + 16 + 4 * qq);
        A[4] = *(const uint*)(hsm + gr * 48 + 32 + 4 * qq);
        A[5] = *(const uint*)(hsm + (gr + 8) * 48 + 32 + 4 * qq);
        __syncwarp();
    }
}

// ---------------- tail layer body (split-2 bf16, f32 acc, exact) -------------
template<bool LAST>
__device__ __forceinline__ void layer_tail(
    const char* __restrict__ bsm,
    const uint (&Ih)[3][4], const uint (&Il)[3][4],
    uint (&Oh)[3][4], uint (&Ol)[3][4],
    int lane, int wp, float* hb)
{
    const int qq = lane & 3;
    const int gr = lane >> 2;
    #pragma unroll
    for (int T = 0; T < 6; T++) {
        float d[3][4];
        #pragma unroll
        for (int g = 0; g < 3; g++) {
            d[g][0] = 0.f; d[g][1] = 0.f; d[g][2] = 0.f; d[g][3] = 0.f;
        }
        #pragma unroll
        for (int g = 0; g < 3; g++)
            #pragma unroll
            for (int Kc = 0; Kc < 3; Kc++) {
                int f2 = (T * 3 + g) * 3 + Kc;
                uint2 vh = *(const uint2*)(bsm + (size_t)f2 * 256 + lane * 8);
                uint2 vl = *(const uint2*)(bsm + HALF_B + (size_t)f2 * 256 + lane * 8);
                mma_bf16(d[g], Ih[Kc], vh.x, vh.y);
                mma_bf16(d[g], Il[Kc], vh.x, vh.y);
                mma_bf16(d[g], Ih[Kc], vl.x, vl.y);
            }
        float h0 = cell_exact(d[0][0], d[1][0], d[2][0]);
        float h1 = cell_exact(d[0][1], d[1][1], d[2][1]);
        float h2 = cell_exact(d[0][2], d[1][2], d[2][2]);
        float h3 = cell_exact(d[0][3], d[1][3], d[2][3]);
        int m0 = T * 8 + 2 * qq;
        if (m0 + 1 == EMB) { h1 = 1.0f; h3 = 1.0f; }
        if (!LAST) {
            int Kc = T >> 1, hh = (T & 1) * 2;
            split_pack(h0, h1, Oh[Kc][hh],     Ol[Kc][hh]);
            split_pack(h2, h3, Oh[Kc][hh + 1], Ol[Kc][hh + 1]);
        } else {
            int e0 = wp * 16 + gr;
            if (m0 < EMB) {
                hb[e0 * 45 + m0]       = h0;
                hb[(e0 + 8) * 45 + m0] = h2;
            }
            if (m0 + 1 < EMB) {
                hb[e0 * 45 + m0 + 1]       = h1;
                hb[(e0 + 8) * 45 + m0 + 1] = h3;
            }
        }
    }
}

__device__ __forceinline__ uint qbyte_emb(const float* emb, int e, int k) {
    if (k < EMB) return q8r(emb[(size_t)e * EMB + k]);
    if (k == 43 || k == 44) return 127u;
    return 0u;
}
template<int N16>
__device__ __forceinline__ void stage(uint sa, const uint* src, int t) {
    const char* g = reinterpret_cast<const char*>(src);
    #pragma unroll
    for (int i = 0; i < (N16 + TPB - 1) / TPB; i++) {
        int idx = t + i * TPB;
        if (idx < N16) cp16(sa + idx * 16, g + (size_t)idx * 16);
    }
    asm volatile("cp.async.commit_group;" ::: "memory");
}
#define STAGE_I(sa, l) stage<N16I>(sa, g_Bi + (size_t)(l) * LIB_U, t)
#define STAGE_T(sa, i) stage<B_LAYER/16>(sa, g_Bf + (size_t)(i) * UPL, t)
#define CP_WAIT() asm volatile("cp.async.wait_group 0;" ::: "memory")

__global__ __launch_bounds__(TPB, 2)
void lstm_table_kernel(const float* __restrict__ emb,
                       const float* __restrict__ w_out,
                       const float* __restrict__ b_out)
{
    extern __shared__ char smem[];
    float* hb     = reinterpret_cast<float*>(smem + SM_T62);   // alias (tail only)
    float* wout_s = reinterpret_cast<float*>(smem + SM_WOUT);
    float* bout_s = reinterpret_cast<float*>(smem + SM_BOUT);

    const int t = threadIdx.x;
    const int wp = t >> 5, lane = t & 31;
    const int gr = lane >> 2, qq = lane & 3;
    const int ebase = blockIdx.x * EPB;

    uint sa0 = smaddr(smem + SM_W0), sa1 = smaddr(smem + SM_W1);
    const char* buf0 = smem + SM_W0;
    const char* buf1 = smem + SM_W1;
    char* hsm = smem + SM_H + wp * 768;

    STAGE_I(sa0, 0);
    for (int i = t; i < OUT_DIM * EMB; i += TPB) wout_s[i] = w_out[i];
    if (t < OUT_DIM) bout_s[t] = b_out[t];

    // initial int8 A fragments from embedding
    uint A[6];
    uint AhX[3][4], AlX[3][4], AhY[3][4], AlY[3][4];
    {
        int e0 = ebase + wp * 16 + gr;
        int ea = (e0 < VOCAB) ? e0 : VOCAB - 1;
        int eb = (e0 + 8 < VOCAB) ? e0 + 8 : VOCAB - 1;
        #pragma unroll
        for (int r = 0; r < 3; r++) {
            int kb = r * 16 + 4 * qq;
            A[2 * r] = qbyte_emb(emb, ea, kb) | (qbyte_emb(emb, ea, kb + 1) << 8)
                     | (qbyte_emb(emb, ea, kb + 2) << 16) | (qbyte_emb(emb, ea, kb + 3) << 24);
            A[2 * r + 1] = qbyte_emb(emb, eb, kb) | (qbyte_emb(emb, eb, kb + 1) << 8)
                     | (qbyte_emb(emb, eb, kb + 2) << 16) | (qbyte_emb(emb, eb, kb + 3) << 24);
        }
    }

    CP_WAIT();
    __syncthreads();

    // layers 0..59: int8 fast path
    #pragma unroll 1
    for (int l = 0; l < 60; l += 2) {
        STAGE_I(sa1, l + 1);
        layer_i8<false>(buf0, hsm, A, AhX, AlX, lane);
        CP_WAIT(); __syncthreads();
        STAGE_I(sa0, l + 2);
        layer_i8<false>(buf1, hsm, A, AhX, AlX, lane);
        CP_WAIT(); __syncthreads();
    }
    // layer 60 (int8): stage 61 + tail62
    STAGE_I(sa1, 61);
    STAGE_T(smaddr(smem + SM_T62), 0);
    layer_i8<false>(buf0, hsm, A, AhX, AlX, lane);
    CP_WAIT(); __syncthreads();
    // layer 61 (int8, split-2 out): stage tail63
    STAGE_T(smaddr(smem + SM_T63), 1);
    layer_i8<true>(buf1, hsm, A, AhX, AlX, lane);
    CP_WAIT(); __syncthreads();
    // layer 62 (split-2, exact)
    layer_tail<false>(smem + SM_T62, AhX, AlX, AhY, AlY, lane, wp, hb);
    __syncthreads();
    // layer 63 (split-2, exact, last) -> hb (aliases T62, free now)
    layer_tail<true>(smem + SM_T63, AhY, AlY, AhX, AlX, lane, wp, hb);
    __syncthreads();

    // ---- head: logits + log_softmax -> g_table ----
    if (t < EPB && ebase + t < VOCAB) {
        float lg[OUT_DIM];
        #pragma unroll
        for (int j = 0; j < OUT_DIM; j++) {
            float a = bout_s[j];
            #pragma unroll
            for (int k = 0; k < EMB; k++)
                a = fmaf(wout_s[j * EMB + k], hb[t * 45 + k], a);
            lg[j] = a;
        }
        float mx = lg[0];
        #pragma unroll
        for (int j = 1; j < OUT_DIM; j++) mx = fmaxf(mx, lg[j]);
        float s = 0.0f;
        #pragma unroll
        for (int j = 0; j < OUT_DIM; j++) s += __expf(lg[j] - mx);
        float lse = mx + __logf(s);
        #pragma unroll
        for (int j = 0; j < OUT_DIM; j++)
            g_table[(size_t)(ebase + t) * OUT_DIM + j] = lg[j] - lse;
    }
}

// ---------------- gather ----------------
__global__ void gather4_kernel(const int* __restrict__ tokens,
                               float4* __restrict__ out4, int n4)
{
    int i = blockIdx.x * blockDim.x + threadIdx.x;
    if (i >= n4) return;
    int base = i * 4;
    float r[4];
    #pragma unroll
    for (int u = 0; u < 4; u++) {
        int idx = base + u;
        int n = idx / OUT_DIM;
        int j = idx - n * OUT_DIM;
        r[u] = g_table[tokens[n] * OUT_DIM + j];
    }
    out4[i] = make_float4(r[0], r[1], r[2], r[3]);
}

extern "C" void kernel_launch(void* const* d_in, const int* in_sizes, int n_in,
                              void* d_out, int out_size)
{
    const int*   tokens = (const int*)  d_in[0];
    const float* emb    = (const float*)d_in[1];
    const float* w_ih   = (const float*)d_in[2];
    // d_in[3] = w_hh : unused (h_prev = 0)
    const float* b_ih   = (const float*)d_in[4];
    const float* b_hh   = (const float*)d_in[5];
    const float* w_out  = (const float*)d_in[6];
    const float* b_out  = (const float*)d_in[7];
    float* out = (float*)d_out;

    prep_kernel<<<78, 256>>>(w_ih, b_ih, b_hh);

    cudaFuncSetAttribute(lstm_table_kernel,
                         cudaFuncAttributeMaxDynamicSharedMemorySize, SM_TOTAL);
    lstm_table_kernel<<<NBLK, TPB, SM_TOTAL>>>(emb, w_out, b_out);

    int n4 = out_size / 4;
    gather4_kernel<<<(n4 + 255) / 256, 256>>>(tokens, (float4*)out, n4);
}

// round 15
// speedup vs baseline: 2.3340x; 2.3340x over previous
#include <cuda_runtime.h>
#include <cstdint>

#define VOCAB   32000
#define EMB     43
#define LAYERS  64
#define OUT_DIM 15

#define TPB     224          // 7 warps, 1 etile/warp -> 112 entries/CTA
#define EPB     112
#define NBLK    286          // 286*112 = 32032 >= 32000; 2 CTAs/SM

#define NF2     54                    // fragments (T,g,Kc) per layer
#define HALF_B  (NF2 * 256)           // 13824 B: one fragment half, dense
#define B_LAYER (2 * HALF_B)          // 27648 B (tail layers: hi half | lo half)
#define UPL     (B_LAYER / 4)         // 6912 uints
#define UHALF   (UPL / 2)             // 3456

// smem layout (bytes)
#define SM_W0    0
#define SM_W1    HALF_B                         // 13824
#define SM_T62   (2 * HALF_B)                   // 27648
#define SM_T63   (SM_T62 + B_LAYER)             // 55296
#define SM_WOUT  (SM_T63 + B_LAYER)             // 82944
#define SM_BOUT  (SM_WOUT + OUT_DIM * EMB * 4)  // 85524
#define SM_TOTAL 85632
// hb (final h, float[112*45] = 20160 B) aliases SM_T62 (free during layer 63)

typedef unsigned int uint;

__device__ float g_table[VOCAB * OUT_DIM];
__device__ uint  g_Bh[(size_t)62 * UHALF];   // f16 frags, layers 0..61 (i/o gates x0.5)
__device__ uint  g_Bf[(size_t)2 * UPL];      // bf16 split-2 frags, layers 62..63

// ---------------- helpers ----------------
__device__ __forceinline__ uint smaddr(const void* p) {
    uint a;
    asm("{ .reg .u64 t; cvta.to.shared.u64 t, %1; cvt.u32.u64 %0, t; }"
        : "=r"(a) : "l"(p));
    return a;
}
__device__ __forceinline__ void cp16(uint sa, const void* g) {
    asm volatile("cp.async.ca.shared.global [%0], [%1], 16;" :: "r"(sa), "l"(g));
}
__device__ __forceinline__ void mma_bf16(float d[4], const uint a[4], uint b0, uint b1) {
    asm volatile(
        "mma.sync.aligned.m16n8k16.row.col.f32.bf16.bf16.f32 "
        "{%0,%1,%2,%3}, {%4,%5,%6,%7}, {%8,%9}, {%0,%1,%2,%3};"
        : "+f"(d[0]), "+f"(d[1]), "+f"(d[2]), "+f"(d[3])
        : "r"(a[0]), "r"(a[1]), "r"(a[2]), "r"(a[3]), "r"(b0), "r"(b1));
}
// f16 accumulator mma: D/C are 2 packed f16x2 regs
__device__ __forceinline__ void mma_f16acc(uint d[2], const uint a[4], uint b0, uint b1) {
    asm volatile(
        "mma.sync.aligned.m16n8k16.row.col.f16.f16.f16.f16 "
        "{%0,%1}, {%2,%3,%4,%5}, {%6,%7}, {%0,%1};"
        : "+r"(d[0]), "+r"(d[1])
        : "r"(a[0]), "r"(a[1]), "r"(a[2]), "r"(a[3]), "r"(b0), "r"(b1));
}
__device__ __forceinline__ uint pack_h2(float hi, float lo) {
    uint d;
    asm("cvt.rn.f16x2.f32 %0, %1, %2;" : "=r"(d) : "f"(hi), "f"(lo));
    return d;
}
__device__ __forceinline__ void split_pack(float x0, float x1, uint& hi, uint& lo) {
    asm("cvt.rn.bf16x2.f32 %0, %1, %2;" : "=r"(hi) : "f"(x1), "f"(x0));
    float r0 = x0 - __uint_as_float(hi << 16);
    float r1 = x1 - __uint_as_float(hi & 0xFFFF0000u);
    asm("cvt.rn.bf16x2.f32 %0, %1, %2;" : "=r"(lo) : "f"(r1), "f"(r0));
}
__device__ __forceinline__ void unpack_h2(uint v, float& lo, float& hi) {
    asm("{ .reg .b16 l, h;\n\t mov.b32 {l, h}, %2;\n\t"
        "cvt.f32.f16 %0, l;\n\t cvt.f32.f16 %1, h; }"
        : "=f"(lo), "=f"(hi) : "r"(v));
}
__device__ __forceinline__ uint tanh2(uint x) {
    uint y;
    asm("tanh.approx.f16x2 %0, %1;" : "=r"(y) : "r"(x));
    return y;
}
__device__ __forceinline__ uint hfma2(uint a, uint b, uint c) {
    uint d;
    asm("fma.rn.f16x2 %0, %1, %2, %3;" : "=r"(d) : "r"(a), "r"(b), "r"(c));
    return d;
}
__device__ __forceinline__ uint hmul2(uint a, uint b) {
    uint d;
    asm("mul.rn.f16x2 %0, %1, %2;" : "=r"(d) : "r"(a), "r"(b));
    return d;
}
#define H05 0x38003800u

// f16x2 LSTM cell pair straight from packed f16x2 gate registers
__device__ __forceinline__ uint cellpair2(uint di, uint dg, uint dq) {
    uint si = hfma2(tanh2(di), H05, H05);     // sigm(i)  (i pre-scaled 0.5)
    uint c  = hmul2(si, tanh2(dg));           // sigm(i)*tanh(g)
    uint so = hfma2(tanh2(dq), H05, H05);     // sigm(o)
    return hmul2(so, tanh2(c));               // h
}
// exact fp32 cell for tail layers
__device__ __forceinline__ float cell_exact(float i, float g, float o) {
    float eg = __expf(-2.0f * fabsf(g));
    float ei = __expf(-i);
    float cc = copysignf(__fdividef(1.0f - eg, (1.0f + ei) * (1.0f + eg)), g);
    float ec = __expf(-2.0f * fabsf(cc));
    float eo = __expf(-o);
    return copysignf(__fdividef(1.0f - ec, (1.0f + eo) * (1.0f + ec)), cc);
}

// -------- frag coordinates: f2 = (T*3+g)*3+Kc ; u = f2*64 + lane*2 + r --------
__device__ __forceinline__ void frag_wval(const float* w_ih, const float* b_ih,
                                          const float* b_hh, int l, int rem,
                                          int& g_out, float& v0, float& v1) {
    int f2   = rem >> 6;
    int lane = (rem >> 1) & 31;
    int r    = rem & 1;
    int Kc = f2 % 3;
    int g  = (f2 / 3) % 3;
    int T  = f2 / 9;
    int m  = T * 8 + (lane >> 2);
    int k0 = Kc * 16 + r * 8 + (lane & 3) * 2;
    v0 = 0.0f; v1 = 0.0f; g_out = g;
    if (m < EMB) {
        int rg = m + (g == 1 ? 86 : (g == 2 ? 129 : 0));   // i / g / o rows
        const float* wr = w_ih + ((size_t)l * 172 + rg) * EMB;
        float bias = b_ih[l * 172 + rg] + b_hh[l * 172 + rg];
        v0 = (k0 < EMB)     ? wr[k0]     : (k0 == EMB     ? bias : 0.0f);
        v1 = (k0 + 1 < EMB) ? wr[k0 + 1] : (k0 + 1 == EMB ? bias : 0.0f);
    }
}

// merged prep: blocks 0..123 -> f16 frags (layers 0..61),
//              blocks 124..139 -> bf16 split-2 frags (layers 62..63)
__global__ void prep_kernel(const float* __restrict__ w_ih,
                            const float* __restrict__ b_ih,
                            const float* __restrict__ b_hh)
{
    int b = blockIdx.x;
    if (b < 124) {
        int l  = b >> 1;
        int u0 = (b & 1) * (UHALF / 2);
        for (int rem = u0 + threadIdx.x; rem < u0 + UHALF / 2; rem += blockDim.x) {
            int g; float v0, v1;
            frag_wval(w_ih, b_ih, b_hh, l, rem, g, v0, v1);
            if (g != 1) { v0 *= 0.5f; v1 *= 0.5f; }    // fold sigm's x/2 into i,o
            g_Bh[(size_t)l * UHALF + rem] = pack_h2(v1, v0);
        }
    } else {
        int bb = b - 124;
        int li = bb >> 3;                      // 0,1 -> layers 62,63
        int u0 = (bb & 7) * (UPL / 8);
        for (int u = u0 + threadIdx.x; u < u0 + UPL / 8; u += blockDim.x) {
            int hl  = (u >= UHALF);
            int rem = u - hl * UHALF;
            int g; float v0, v1;
            frag_wval(w_ih, b_ih, b_hh, 62 + li, rem, g, v0, v1);
            uint hi;
            asm("cvt.rn.bf16x2.f32 %0, %1, %2;" : "=r"(hi) : "f"(v1), "f"(v0));
            uint outv = hi;
            if (hl) {
                float r0 = v0 - __uint_as_float(hi << 16);
                float r1 = v1 - __uint_as_float(hi & 0xFFFF0000u);
                asm("cvt.rn.bf16x2.f32 %0, %1, %2;" : "=r"(outv) : "f"(r1), "f"(r0));
            }
            g_Bf[(size_t)li * UPL + u] = outv;
        }
    }
}

// ---------------- f16 layer body (layers 0..61), f16 accumulator -------------
template<bool OUTSPLIT>
__device__ __forceinline__ void layer_f16(
    const char* __restrict__ bsm,
    const uint (&Ih)[3][4],
    uint (&Oh)[3][4], uint (&Ol)[3][4],
    int lane)
{
    const int qq = lane & 3;
    #pragma unroll
    for (int T = 0; T < 6; T++) {
        uint dd[3][2];
        #pragma unroll
        for (int g = 0; g < 3; g++) { dd[g][0] = 0u; dd[g][1] = 0u; }
        #pragma unroll
        for (int g = 0; g < 3; g++)
            #pragma unroll
            for (int Kc = 0; Kc < 3; Kc++) {
                uint2 B = *(const uint2*)(bsm + (size_t)(((T*3+g)*3+Kc)) * 256 + lane * 8);
                mma_f16acc(dd[g], Ih[Kc], B.x, B.y);
            }
        // packed D registers ARE the f16x2 gate pairs: no cvt needed
        uint p0 = cellpair2(dd[0][0], dd[1][0], dd[2][0]);   // row gr,   cols m0,m0+1
        uint p1 = cellpair2(dd[0][1], dd[1][1], dd[2][1]);   // row gr+8
        int m0 = T * 8 + 2 * qq;
        if (m0 + 1 == EMB) {               // k=43 "one" column (f16 1.0 hi half)
            p0 = (p0 & 0xFFFFu) | 0x3C000000u;
            p1 = (p1 & 0xFFFFu) | 0x3C000000u;
        }
        int Kc = T >> 1, hh = (T & 1) * 2;
        if (!OUTSPLIT) {
            Oh[Kc][hh]     = p0;
            Oh[Kc][hh + 1] = p1;
        } else {
            float a0, a1, b0, b1;
            unpack_h2(p0, a0, a1);
            unpack_h2(p1, b0, b1);
            split_pack(a0, a1, Oh[Kc][hh],     Ol[Kc][hh]);
            split_pack(b0, b1, Oh[Kc][hh + 1], Ol[Kc][hh + 1]);
        }
    }
}

// ---------------- tail layer body (split-2 bf16, f32 acc, exact cells) -------
template<bool LAST>
__device__ __forceinline__ void layer_tail(
    const char* __restrict__ bsm,
    const uint (&Ih)[3][4], const uint (&Il)[3][4],
    uint (&Oh)[3][4], uint (&Ol)[3][4],
    int lane, int wp, float* hb)
{
    const int qq = lane & 3;
    const int gr = lane >> 2;
    #pragma unroll
    for (int T = 0; T < 6; T++) {
        float d[3][4];
        #pragma unroll
        for (int g = 0; g < 3; g++) {
            d[g][0] = 0.f; d[g][1] = 0.f; d[g][2] = 0.f; d[g][3] = 0.f;
        }
        #pragma unroll
        for (int g = 0; g < 3; g++)
            #pragma unroll
            for (int Kc = 0; Kc < 3; Kc++) {
                int f2 = (T * 3 + g) * 3 + Kc;
                uint2 vh = *(const uint2*)(bsm + (size_t)f2 * 256 + lane * 8);
                uint2 vl = *(const uint2*)(bsm + HALF_B + (size_t)f2 * 256 + lane * 8);
                mma_bf16(d[g], Ih[Kc], vh.x, vh.y);
                mma_bf16(d[g], Il[Kc], vh.x, vh.y);
                mma_bf16(d[g], Ih[Kc], vl.x, vl.y);
            }
        float h0 = cell_exact(d[0][0], d[1][0], d[2][0]);
        float h1 = cell_exact(d[0][1], d[1][1], d[2][1]);
        float h2 = cell_exact(d[0][2], d[1][2], d[2][2]);
        float h3 = cell_exact(d[0][3], d[1][3], d[2][3]);
        int m0 = T * 8 + 2 * qq;
        if (m0 + 1 == EMB) { h1 = 1.0f; h3 = 1.0f; }
        if (!LAST) {
            int Kc = T >> 1, hh = (T & 1) * 2;
            split_pack(h0, h1, Oh[Kc][hh],     Ol[Kc][hh]);
            split_pack(h2, h3, Oh[Kc][hh + 1], Ol[Kc][hh + 1]);
        } else {
            int e0 = wp * 16 + gr;
            if (m0 < EMB) {
                hb[e0 * 45 + m0]       = h0;
                hb[(e0 + 8) * 45 + m0] = h2;
            }
            if (m0 + 1 < EMB) {
                hb[e0 * 45 + m0 + 1]       = h1;
                hb[(e0 + 8) * 45 + m0 + 1] = h3;
            }
        }
    }
}

__device__ __forceinline__ float fetch_emb(const float* emb, int e, int k) {
    if (k < EMB)  return emb[(size_t)e * EMB + k];
    if (k == EMB) return 1.0f;
    return 0.0f;
}
template<int N16>
__device__ __forceinline__ void stage(uint sa, const uint* src, int t) {
    const char* g = reinterpret_cast<const char*>(src);
    #pragma unroll
    for (int i = 0; i < (N16 + TPB - 1) / TPB; i++) {
        int idx = t + i * TPB;
        if (idx < N16) cp16(sa + idx * 16, g + (size_t)idx * 16);
    }
    asm volatile("cp.async.commit_group;" ::: "memory");
}
#define STAGE_H16(sa, l) stage<HALF_B/16>(sa, g_Bh + (size_t)(l) * UHALF, t)
#define STAGE_T(sa, i)   stage<B_LAYER/16>(sa, g_Bf + (size_t)(i) * UPL, t)
#define CP_WAIT() asm volatile("cp.async.wait_group 0;" ::: "memory")

__global__ __launch_bounds__(TPB, 2)
void lstm_table_kernel(const float* __restrict__ emb,
                       const float* __restrict__ w_out,
                       const float* __restrict__ b_out)
{
    extern __shared__ char smem[];
    float* hb     = reinterpret_cast<float*>(smem + SM_T62);   // alias (layer-63 only)
    float* wout_s = reinterpret_cast<float*>(smem + SM_WOUT);
    float* bout_s = reinterpret_cast<float*>(smem + SM_BOUT);

    const int t = threadIdx.x;
    const int wp = t >> 5, lane = t & 31;
    const int gr = lane >> 2, qq = lane & 3;
    const int ebase = blockIdx.x * EPB;

    uint sa0 = smaddr(smem + SM_W0), sa1 = smaddr(smem + SM_W1);
    const char* buf0 = smem + SM_W0;
    const char* buf1 = smem + SM_W1;

    STAGE_H16(sa0, 0);                         // layer 0
    for (int i = t; i < OUT_DIM * EMB; i += TPB) wout_s[i] = w_out[i];
    if (t < OUT_DIM) bout_s[t] = b_out[t];

    // initial A fragments from embedding (f16), 1 etile per warp
    uint AhX[3][4], AlX[3][4], AhY[3][4], AlY[3][4];
    {
        int e0 = ebase + wp * 16 + gr;
        int ea = (e0 < VOCAB) ? e0 : VOCAB - 1;
        int eb = (e0 + 8 < VOCAB) ? e0 + 8 : VOCAB - 1;
        #pragma unroll
        for (int Kc = 0; Kc < 3; Kc++)
            #pragma unroll
            for (int hh = 0; hh < 2; hh++) {
                int k = Kc * 16 + hh * 8 + 2 * qq;
                AhX[Kc][hh * 2]     = pack_h2(fetch_emb(emb, ea, k + 1),
                                              fetch_emb(emb, ea, k));
                AhX[Kc][hh * 2 + 1] = pack_h2(fetch_emb(emb, eb, k + 1),
                                              fetch_emb(emb, eb, k));
            }
    }

    CP_WAIT();
    __syncthreads();

    // layers 0..59: f16 fast path (f16 accumulator)
    #pragma unroll 1
    for (int l = 0; l < 60; l += 2) {
        STAGE_H16(sa1, l + 1);
        layer_f16<false>(buf0, AhX, AhY, AlY, lane);
        CP_WAIT(); __syncthreads();
        STAGE_H16(sa0, l + 2);
        layer_f16<false>(buf1, AhY, AhX, AlX, lane);
        CP_WAIT(); __syncthreads();
    }
    // l = 60 (f16): stage 61 + tail layer 62 frags
    STAGE_H16(sa1, 61);
    STAGE_T(smaddr(smem + SM_T62), 0);
    layer_f16<false>(buf0, AhX, AhY, AlY, lane);
    CP_WAIT(); __syncthreads();
    // l = 61 (f16 in, split-2 bf16 out): stage tail layer 63 frags
    STAGE_T(smaddr(smem + SM_T63), 1);
    layer_f16<true>(buf1, AhY, AhX, AlX, lane);
    CP_WAIT(); __syncthreads();
    // l = 62 (split-2, exact)
    layer_tail<false>(smem + SM_T62, AhX, AlX, AhY, AlY, lane, wp, hb);
    __syncthreads();
    // l = 63 (split-2, exact, last) -> hb (aliases T62, free now)
    layer_tail<true>(smem + SM_T63, AhY, AlY, AhX, AlX, lane, wp, hb);
    __syncthreads();

    // ---- head: logits + log_softmax -> g_table ----
    if (t < EPB && ebase + t < VOCAB) {
        float lg[OUT_DIM];
        #pragma unroll
        for (int j = 0; j < OUT_DIM; j++) {
            float a = bout_s[j];
            #pragma unroll
            for (int k = 0; k < EMB; k++)
                a = fmaf(wout_s[j * EMB + k], hb[t * 45 + k], a);
            lg[j] = a;
        }
        float mx = lg[0];
        #pragma unroll
        for (int j = 1; j < OUT_DIM; j++) mx = fmaxf(mx, lg[j]);
        float s = 0.0f;
        #pragma unroll
        for (int j = 0; j < OUT_DIM; j++) s += __expf(lg[j] - mx);
        float lse = mx + __logf(s);
        #pragma unroll
        for (int j = 0; j < OUT_DIM; j++)
            g_table[(size_t)(ebase + t) * OUT_DIM + j] = lg[j] - lse;
    }
}

// ---------------- gather: 8 floats (2 independent float4 chains) per thread --
__global__ void gather8_kernel(const int* __restrict__ tokens,
                               float4* __restrict__ out4, int n4)
{
    int i0 = (blockIdx.x * blockDim.x + threadIdx.x) * 2;
    #pragma unroll
    for (int v = 0; v < 2; v++) {
        int i = i0 + v;
        if (i >= n4) break;
        int base = i * 4;
        float r[4];
        #pragma unroll
        for (int u = 0; u < 4; u++) {
            int idx = base + u;
            int n = idx / OUT_DIM;
            int j = idx - n * OUT_DIM;
            r[u] = g_table[tokens[n] * OUT_DIM + j];
        }
        out4[i] = make_float4(r[0], r[1], r[2], r[3]);
    }
}

extern "C" void kernel_launch(void* const* d_in, const int* in_sizes, int n_in,
                              void* d_out, int out_size)
{
    const int*   tokens = (const int*)  d_in[0];
    const float* emb    = (const float*)d_in[1];
    const float* w_ih   = (const float*)d_in[2];
    // d_in[3] = w_hh : unused (h_prev = 0)
    const float* b_ih   = (const float*)d_in[4];
    const float* b_hh   = (const float*)d_in[5];
    const float* w_out  = (const float*)d_in[6];
    const float* b_out  = (const float*)d_in[7];
    float* out = (float*)d_out;

    prep_kernel<<<140, 256>>>(w_ih, b_ih, b_hh);

    cudaFuncSetAttribute(lstm_table_kernel,
                         cudaFuncAttributeMaxDynamicSharedMemorySize, SM_TOTAL);
    lstm_table_kernel<<<NBLK, TPB, SM_TOTAL>>>(emb, w_out, b_out);

    int n4 = out_size / 4;
    int nthread = (n4 + 1) / 2;
    gather8_kernel<<<(nthread + 255) / 256, 256>>>(tokens, (float4*)out, n4);
}

// round 16
// speedup vs baseline: 2.4362x; 1.0438x over previous
#include <cuda_runtime.h>
#include <cstdint>

#define VOCAB   32000
#define EMB     43
#define LAYERS  64
#define OUT_DIM 15

#define TPB     224          // 7 warps, 1 etile/warp -> 112 entries/CTA
#define EPB     112
#define NBLK    286          // 286*112 = 32032 >= 32000; 2 CTAs/SM

#define NF2     54                    // fragments (T,g,Kc) per layer
#define HALF_B  (NF2 * 256)           // 13824 B: one fragment half, dense
#define B_LAYER (2 * HALF_B)          // 27648 B (tail layers: hi half | lo half)
#define UPL     (B_LAYER / 4)         // 6912 uints
#define UHALF   (UPL / 2)             // 3456

// smem layout (bytes)  — identical to the 147.5us R13 configuration
#define SM_B0    0
#define SM_B1    B_LAYER
#define SM_HB    (2 * B_LAYER)                  // 55296 : float[112*45] = 20160
#define SM_WOUT  (SM_HB + 112 * 45 * 4)         // 75456
#define SM_BOUT  (SM_WOUT + OUT_DIM * EMB * 4)  // 78036
#define SM_TOTAL 78144

typedef unsigned int uint;

__device__ float g_table[VOCAB * OUT_DIM];
__device__ uint  g_Bh[(size_t)62 * UHALF];   // f16 frags, layers 0..61 (i/o gates x0.5)
__device__ uint  g_Bf[(size_t)2 * UPL];      // bf16 split-2 frags, layers 62..63

// ---------------- helpers ----------------
__device__ __forceinline__ uint smaddr(const void* p) {
    uint a;
    asm("{ .reg .u64 t; cvta.to.shared.u64 t, %1; cvt.u32.u64 %0, t; }"
        : "=r"(a) : "l"(p));
    return a;
}
__device__ __forceinline__ void cp16(uint sa, const void* g) {
    asm volatile("cp.async.ca.shared.global [%0], [%1], 16;" :: "r"(sa), "l"(g));
}
__device__ __forceinline__ void mma_bf16(float d[4], const uint a[4], uint b0, uint b1) {
    asm volatile(
        "mma.sync.aligned.m16n8k16.row.col.f32.bf16.bf16.f32 "
        "{%0,%1,%2,%3}, {%4,%5,%6,%7}, {%8,%9}, {%0,%1,%2,%3};"
        : "+f"(d[0]), "+f"(d[1]), "+f"(d[2]), "+f"(d[3])
        : "r"(a[0]), "r"(a[1]), "r"(a[2]), "r"(a[3]), "r"(b0), "r"(b1));
}
// f16 accumulator mma: D/C are 2 packed f16x2 regs
__device__ __forceinline__ void mma_f16acc(uint d[2], const uint a[4], uint b0, uint b1) {
    asm volatile(
        "mma.sync.aligned.m16n8k16.row.col.f16.f16.f16.f16 "
        "{%0,%1}, {%2,%3,%4,%5}, {%6,%7}, {%0,%1};"
        : "+r"(d[0]), "+r"(d[1])
        : "r"(a[0]), "r"(a[1]), "r"(a[2]), "r"(a[3]), "r"(b0), "r"(b1));
}
__device__ __forceinline__ uint pack_h2(float hi, float lo) {
    uint d;
    asm("cvt.rn.f16x2.f32 %0, %1, %2;" : "=r"(d) : "f"(hi), "f"(lo));
    return d;
}
__device__ __forceinline__ void split_pack(float x0, float x1, uint& hi, uint& lo) {
    asm("cvt.rn.bf16x2.f32 %0, %1, %2;" : "=r"(hi) : "f"(x1), "f"(x0));
    float r0 = x0 - __uint_as_float(hi << 16);
    float r1 = x1 - __uint_as_float(hi & 0xFFFF0000u);
    asm("cvt.rn.bf16x2.f32 %0, %1, %2;" : "=r"(lo) : "f"(r1), "f"(r0));
}
__device__ __forceinline__ void unpack_h2(uint v, float& lo, float& hi) {
    asm("{ .reg .b16 l, h;\n\t mov.b32 {l, h}, %2;\n\t"
        "cvt.f32.f16 %0, l;\n\t cvt.f32.f16 %1, h; }"
        : "=f"(lo), "=f"(hi) : "r"(v));
}
__device__ __forceinline__ uint tanh2(uint x) {
    uint y;
    asm("tanh.approx.f16x2 %0, %1;" : "=r"(y) : "r"(x));
    return y;
}
__device__ __forceinline__ uint hfma2(uint a, uint b, uint c) {
    uint d;
    asm("fma.rn.f16x2 %0, %1, %2, %3;" : "=r"(d) : "r"(a), "r"(b), "r"(c));
    return d;
}
__device__ __forceinline__ uint hmul2(uint a, uint b) {
    uint d;
    asm("mul.rn.f16x2 %0, %1, %2;" : "=r"(d) : "r"(a), "r"(b));
    return d;
}
#define H05 0x38003800u

// f16x2 LSTM cell pair straight from packed f16x2 gate registers
__device__ __forceinline__ uint cellpair2(uint di, uint dg, uint dq) {
    uint si = hfma2(tanh2(di), H05, H05);     // sigm(i)  (i pre-scaled 0.5)
    uint c  = hmul2(si, tanh2(dg));           // sigm(i)*tanh(g)
    uint so = hfma2(tanh2(dq), H05, H05);     // sigm(o)
    return hmul2(so, tanh2(c));               // h
}
// exact fp32 cell for tail layers
__device__ __forceinline__ float cell_exact(float i, float g, float o) {
    float eg = __expf(-2.0f * fabsf(g));
    float ei = __expf(-i);
    float cc = copysignf(__fdividef(1.0f - eg, (1.0f + ei) * (1.0f + eg)), g);
    float ec = __expf(-2.0f * fabsf(cc));
    float eo = __expf(-o);
    return copysignf(__fdividef(1.0f - ec, (1.0f + eo) * (1.0f + ec)), cc);
}

// -------- frag coordinates: f2 = (T*3+g)*3+Kc ; u = f2*64 + lane*2 + r --------
__device__ __forceinline__ void frag_wval(const float* w_ih, const float* b_ih,
                                          const float* b_hh, int l, int rem,
                                          int& g_out, float& v0, float& v1) {
    int f2   = rem >> 6;
    int lane = (rem >> 1) & 31;
    int r    = rem & 1;
    int Kc = f2 % 3;
    int g  = (f2 / 3) % 3;
    int T  = f2 / 9;
    int m  = T * 8 + (lane >> 2);
    int k0 = Kc * 16 + r * 8 + (lane & 3) * 2;
    v0 = 0.0f; v1 = 0.0f; g_out = g;
    if (m < EMB) {
        int rg = m + (g == 1 ? 86 : (g == 2 ? 129 : 0));   // i / g / o rows
        const float* wr = w_ih + ((size_t)l * 172 + rg) * EMB;
        float bias = b_ih[l * 172 + rg] + b_hh[l * 172 + rg];
        v0 = (k0 < EMB)     ? wr[k0]     : (k0 == EMB     ? bias : 0.0f);
        v1 = (k0 + 1 < EMB) ? wr[k0 + 1] : (k0 + 1 == EMB ? bias : 0.0f);
    }
}

// merged prep, finer split: blocks 0..247 -> f16 frags (4 blocks/layer),
//                           blocks 248..263 -> bf16 split-2 tail frags
__global__ void prep_kernel(const float* __restrict__ w_ih,
                            const float* __restrict__ b_ih,
                            const float* __restrict__ b_hh)
{
    int b = blockIdx.x;
    if (b < 248) {
        int l  = b >> 2;
        int u0 = (b & 3) * (UHALF / 4);
        for (int rem = u0 + threadIdx.x; rem < u0 + UHALF / 4; rem += blockDim.x) {
            int g; float v0, v1;
            frag_wval(w_ih, b_ih, b_hh, l, rem, g, v0, v1);
            if (g != 1) { v0 *= 0.5f; v1 *= 0.5f; }    // fold sigm's x/2 into i,o
            g_Bh[(size_t)l * UHALF + rem] = pack_h2(v1, v0);
        }
    } else {
        int bb = b - 248;
        int li = bb >> 3;                      // 0,1 -> layers 62,63
        int u0 = (bb & 7) * (UPL / 8);
        for (int u = u0 + threadIdx.x; u < u0 + UPL / 8; u += blockDim.x) {
            int hl  = (u >= UHALF);
            int rem = u - hl * UHALF;
            int g; float v0, v1;
            frag_wval(w_ih, b_ih, b_hh, 62 + li, rem, g, v0, v1);
            uint hi;
            asm("cvt.rn.bf16x2.f32 %0, %1, %2;" : "=r"(hi) : "f"(v1), "f"(v0));
            uint outv = hi;
            if (hl) {
                float r0 = v0 - __uint_as_float(hi << 16);
                float r1 = v1 - __uint_as_float(hi & 0xFFFF0000u);
                asm("cvt.rn.bf16x2.f32 %0, %1, %2;" : "=r"(outv) : "f"(r1), "f"(r0));
            }
            g_Bf[(size_t)li * UPL + u] = outv;
        }
    }
}

// ---------------- f16 layer body (layers 0..61), f16 accumulator -------------
template<bool OUTSPLIT>
__device__ __forceinline__ void layer_f16(
    const char* __restrict__ bsm,
    const uint (&Ih)[3][4],
    uint (&Oh)[3][4], uint (&Ol)[3][4],
    int lane)
{
    const int qq = lane & 3;
    #pragma unroll
    for (int T = 0; T < 6; T++) {
        uint dd[3][2];
        #pragma unroll
        for (int g = 0; g < 3; g++) { dd[g][0] = 0u; dd[g][1] = 0u; }
        #pragma unroll
        for (int g = 0; g < 3; g++)
            #pragma unroll
            for (int Kc = 0; Kc < 3; Kc++) {
                uint2 B = *(const uint2*)(bsm + (size_t)(((T*3+g)*3+Kc)) * 256 + lane * 8);
                mma_f16acc(dd[g], Ih[Kc], B.x, B.y);
            }
        // packed D registers ARE the f16x2 gate pairs: no cvt needed
        uint p0 = cellpair2(dd[0][0], dd[1][0], dd[2][0]);   // row gr,   cols m0,m0+1
        uint p1 = cellpair2(dd[0][1], dd[1][1], dd[2][1]);   // row gr+8
        int m0 = T * 8 + 2 * qq;
        if (m0 + 1 == EMB) {               // k=43 "one" column (f16 1.0 hi half)
            p0 = (p0 & 0xFFFFu) | 0x3C000000u;
            p1 = (p1 & 0xFFFFu) | 0x3C000000u;
        }
        int Kc = T >> 1, hh = (T & 1) * 2;
        if (!OUTSPLIT) {
            Oh[Kc][hh]     = p0;
            Oh[Kc][hh + 1] = p1;
        } else {
            float a0, a1, b0, b1;
            unpack_h2(p0, a0, a1);
            unpack_h2(p1, b0, b1);
            split_pack(a0, a1, Oh[Kc][hh],     Ol[Kc][hh]);
            split_pack(b0, b1, Oh[Kc][hh + 1], Ol[Kc][hh + 1]);
        }
    }
}

// ---------------- tail layer body (split-2 bf16, f32 acc, exact cells) -------
template<bool LAST>
__device__ __forceinline__ void layer_tail(
    const char* __restrict__ bsm,
    const uint (&Ih)[3][4], const uint (&Il)[3][4],
    uint (&Oh)[3][4], uint (&Ol)[3][4],
    int lane, int wp, float* hb)
{
    const int qq = lane & 3;
    const int gr = lane >> 2;
    #pragma unroll
    for (int T = 0; T < 6; T++) {
        float d[3][4];
        #pragma unroll
        for (int g = 0; g < 3; g++) {
            d[g][0] = 0.f; d[g][1] = 0.f; d[g][2] = 0.f; d[g][3] = 0.f;
        }
        #pragma unroll
        for (int g = 0; g < 3; g++)
            #pragma unroll
            for (int Kc = 0; Kc < 3; Kc++) {
                int f2 = (T * 3 + g) * 3 + Kc;
                uint2 vh = *(const uint2*)(bsm + (size_t)f2 * 256 + lane * 8);
                uint2 vl = *(const uint2*)(bsm + HALF_B + (size_t)f2 * 256 + lane * 8);
                mma_bf16(d[g], Ih[Kc], vh.x, vh.y);
                mma_bf16(d[g], Il[Kc], vh.x, vh.y);
                mma_bf16(d[g], Ih[Kc], vl.x, vl.y);
            }
        float h0 = cell_exact(d[0][0], d[1][0], d[2][0]);
        float h1 = cell_exact(d[0][1], d[1][1], d[2][1]);
        float h2 = cell_exact(d[0][2], d[1][2], d[2][2]);
        float h3 = cell_exact(d[0][3], d[1][3], d[2][3]);
        int m0 = T * 8 + 2 * qq;
        if (m0 + 1 == EMB) { h1 = 1.0f; h3 = 1.0f; }
        if (!LAST) {
            int Kc = T >> 1, hh = (T & 1) * 2;
            split_pack(h0, h1, Oh[Kc][hh],     Ol[Kc][hh]);
            split_pack(h2, h3, Oh[Kc][hh + 1], Ol[Kc][hh + 1]);
        } else {
            int e0 = wp * 16 + gr;
            if (m0 < EMB) {
                hb[e0 * 45 + m0]       = h0;
                hb[(e0 + 8) * 45 + m0] = h2;
            }
            if (m0 + 1 < EMB) {
                hb[e0 * 45 + m0 + 1]       = h1;
                hb[(e0 + 8) * 45 + m0 + 1] = h3;
            }
        }
    }
}

__device__ __forceinline__ float fetch_emb(const float* emb, int e, int k) {
    if (k < EMB)  return emb[(size_t)e * EMB + k];
    if (k == EMB) return 1.0f;
    return 0.0f;
}
template<int N16>
__device__ __forceinline__ void stage(uint sa, const uint* src, int t) {
    const char* g = reinterpret_cast<const char*>(src);
    #pragma unroll
    for (int i = 0; i < (N16 + TPB - 1) / TPB; i++) {
        int idx = t + i * TPB;
        if (idx < N16) cp16(sa + idx * 16, g + (size_t)idx * 16);
    }
    asm volatile("cp.async.commit_group;" ::: "memory");
}
#define STAGE_H16(sa, l) stage<HALF_B/16>(sa, g_Bh + (size_t)(l) * UHALF, t)
#define STAGE_F(sa, i)   stage<B_LAYER/16>(sa, g_Bf + (size_t)(i) * UPL, t)
#define CP_WAIT() asm volatile("cp.async.wait_group 0;" ::: "memory")

__global__ __launch_bounds__(TPB, 2)
void lstm_table_kernel(const float* __restrict__ emb,
                       const float* __restrict__ w_out,
                       const float* __restrict__ b_out)
{
    extern __shared__ char smem[];
    float* hb     = reinterpret_cast<float*>(smem + SM_HB);
    float* wout_s = reinterpret_cast<float*>(smem + SM_WOUT);
    float* bout_s = reinterpret_cast<float*>(smem + SM_BOUT);

    const int t = threadIdx.x;
    const int wp = t >> 5, lane = t & 31;
    const int gr = lane >> 2, qq = lane & 3;
    const int ebase = blockIdx.x * EPB;

    uint sa0 = smaddr(smem + SM_B0), sa1 = smaddr(smem + SM_B1);
    const char* buf0 = smem + SM_B0;
    const char* buf1 = smem + SM_B1;

    STAGE_H16(sa0, 0);                         // layer 0
    for (int i = t; i < OUT_DIM * EMB; i += TPB) wout_s[i] = w_out[i];
    if (t < OUT_DIM) bout_s[t] = b_out[t];

    // initial A fragments from embedding (f16), 1 etile per warp
    uint AhX[3][4], AlX[3][4], AhY[3][4], AlY[3][4];
    {
        int e0 = ebase + wp * 16 + gr;
        int ea = (e0 < VOCAB) ? e0 : VOCAB - 1;
        int eb = (e0 + 8 < VOCAB) ? e0 + 8 : VOCAB - 1;
        #pragma unroll
        for (int Kc = 0; Kc < 3; Kc++)
            #pragma unroll
            for (int hh = 0; hh < 2; hh++) {
                int k = Kc * 16 + hh * 8 + 2 * qq;
                AhX[Kc][hh * 2]     = pack_h2(fetch_emb(emb, ea, k + 1),
                                              fetch_emb(emb, ea, k));
                AhX[Kc][hh * 2 + 1] = pack_h2(fetch_emb(emb, eb, k + 1),
                                              fetch_emb(emb, eb, k));
            }
    }

    CP_WAIT();
    __syncthreads();

    // layers 0..59: f16 fast path (f16 accumulator)
    #pragma unroll 1
    for (int l = 0; l < 60; l += 2) {
        STAGE_H16(sa1, l + 1);
        layer_f16<false>(buf0, AhX, AhY, AlY, lane);
        CP_WAIT(); __syncthreads();
        STAGE_H16(sa0, l + 2);
        layer_f16<false>(buf1, AhY, AhX, AlX, lane);
        CP_WAIT(); __syncthreads();
    }
    // l = 60 (f16)
    STAGE_H16(sa1, 61);
    layer_f16<false>(buf0, AhX, AhY, AlY, lane);
    CP_WAIT(); __syncthreads();
    // l = 61 (f16 in, split-2 bf16 out)
    STAGE_F(sa0, 0);                           // layer 62 tail frags
    layer_f16<true>(buf1, AhY, AhX, AlX, lane);
    CP_WAIT(); __syncthreads();
    // l = 62 (split-2, exact)
    STAGE_F(sa1, 1);                           // layer 63 tail frags
    layer_tail<false>(buf0, AhX, AlX, AhY, AlY, lane, wp, hb);
    CP_WAIT(); __syncthreads();
    // l = 63 (split-2, exact, last) -> hb
    layer_tail<true>(buf1, AhY, AlY, AhX, AlX, lane, wp, hb);
    __syncthreads();

    // ---- head: logits + log_softmax -> g_table ----
    if (t < EPB && ebase + t < VOCAB) {
        float lg[OUT_DIM];
        #pragma unroll
        for (int j = 0; j < OUT_DIM; j++) {
            float a = bout_s[j];
            #pragma unroll
            for (int k = 0; k < EMB; k++)
                a = fmaf(wout_s[j * EMB + k], hb[t * 45 + k], a);
            lg[j] = a;
        }
        float mx = lg[0];
        #pragma unroll
        for (int j = 1; j < OUT_DIM; j++) mx = fmaxf(mx, lg[j]);
        float s = 0.0f;
        #pragma unroll
        for (int j = 0; j < OUT_DIM; j++) s += __expf(lg[j] - mx);
        float lse = mx + __logf(s);
        #pragma unroll
        for (int j = 0; j < OUT_DIM; j++)
            g_table[(size_t)(ebase + t) * OUT_DIM + j] = lg[j] - lse;
    }
}

// ---------------- gather: single launch, streaming stores ----------------
__global__ void gather4_kernel(const int* __restrict__ tokens,
                               float4* __restrict__ out4, int n4)
{
    int i = blockIdx.x * blockDim.x + threadIdx.x;
    if (i >= n4) return;
    int base = i * 4;
    float r[4];
    #pragma unroll
    for (int u = 0; u < 4; u++) {
        int idx = base + u;
        int n = idx / OUT_DIM;
        int j = idx - n * OUT_DIM;
        r[u] = __ldg(&g_table[__ldg(&tokens[n]) * OUT_DIM + j]);
    }
    float4 v = make_float4(r[0], r[1], r[2], r[3]);
    asm volatile("st.global.cs.v4.f32 [%0], {%1,%2,%3,%4};"
                 :: "l"(out4 + i), "f"(v.x), "f"(v.y), "f"(v.z), "f"(v.w)
                 : "memory");
}

extern "C" void kernel_launch(void* const* d_in, const int* in_sizes, int n_in,
                              void* d_out, int out_size)
{
    const int*   tokens = (const int*)  d_in[0];
    const float* emb    = (const float*)d_in[1];
    const float* w_ih   = (const float*)d_in[2];
    // d_in[3] = w_hh : unused (h_prev = 0)
    const float* b_ih   = (const float*)d_in[4];
    const float* b_hh   = (const float*)d_in[5];
    const float* w_out  = (const float*)d_in[6];
    const float* b_out  = (const float*)d_in[7];
    float* out = (float*)d_out;

    prep_kernel<<<264, 256>>>(w_ih, b_ih, b_hh);

    cudaFuncSetAttribute(lstm_table_kernel,
                         cudaFuncAttributeMaxDynamicSharedMemorySize, SM_TOTAL);
    lstm_table_kernel<<<NBLK, TPB, SM_TOTAL>>>(emb, w_out, b_out);

    int n4 = out_size / 4;
    gather4_kernel<<<(n4 + 255) / 256, 256>>>(tokens, (float4*)out, n4);
}

// round 17
// speedup vs baseline: 2.4949x; 1.0241x over previous
#include <cuda_runtime.h>
#include <cstdint>

#define VOCAB   32000
#define EMB     43
#define LAYERS  64
#define OUT_DIM 15

#define TPB     224          // 7 warps, 1 etile/warp -> 112 entries/CTA
#define EPB     112
#define NBLK    286          // 286*112 = 32032 >= 32000; 2 CTAs/SM

#define NF2     54                    // fragments (T,g,Kc) per layer
#define HALF_B  (NF2 * 256)           // 13824 B per layer (f16 frags, dense)
#define UHALF   (HALF_B / 4)          // 3456 uints

// smem layout (bytes)
#define SM_B0    0
#define SM_B1    HALF_B                         // 13824
#define SM_HB    (2 * HALF_B)                   // 27648 : float[112*45] = 20160
#define SM_WOUT  (SM_HB + 112 * 45 * 4)         // 47808
#define SM_BOUT  (SM_WOUT + OUT_DIM * EMB * 4)  // 50388
#define SM_TOTAL 50496

typedef unsigned int uint;

__device__ float g_table[VOCAB * OUT_DIM];
__device__ uint  g_Bh[(size_t)LAYERS * UHALF];  // f16 frags, ALL layers (i/o x0.5)

// ---------------- helpers ----------------
__device__ __forceinline__ uint smaddr(const void* p) {
    uint a;
    asm("{ .reg .u64 t; cvta.to.shared.u64 t, %1; cvt.u32.u64 %0, t; }"
        : "=r"(a) : "l"(p));
    return a;
}
__device__ __forceinline__ void cp16(uint sa, const void* g) {
    asm volatile("cp.async.ca.shared.global [%0], [%1], 16;" :: "r"(sa), "l"(g));
}
// f16 accumulator mma: D/C are 2 packed f16x2 regs
__device__ __forceinline__ void mma_f16acc(uint d[2], const uint a[4], uint b0, uint b1) {
    asm volatile(
        "mma.sync.aligned.m16n8k16.row.col.f16.f16.f16.f16 "
        "{%0,%1}, {%2,%3,%4,%5}, {%6,%7}, {%0,%1};"
        : "+r"(d[0]), "+r"(d[1])
        : "r"(a[0]), "r"(a[1]), "r"(a[2]), "r"(a[3]), "r"(b0), "r"(b1));
}
// f32 accumulator mma on the same f16 fragments (tail layers)
__device__ __forceinline__ void mma_f16f32(float d[4], const uint a[4], uint b0, uint b1) {
    asm volatile(
        "mma.sync.aligned.m16n8k16.row.col.f32.f16.f16.f32 "
        "{%0,%1,%2,%3}, {%4,%5,%6,%7}, {%8,%9}, {%0,%1,%2,%3};"
        : "+f"(d[0]), "+f"(d[1]), "+f"(d[2]), "+f"(d[3])
        : "r"(a[0]), "r"(a[1]), "r"(a[2]), "r"(a[3]), "r"(b0), "r"(b1));
}
__device__ __forceinline__ uint pack_h2(float hi, float lo) {
    uint d;
    asm("cvt.rn.f16x2.f32 %0, %1, %2;" : "=r"(d) : "f"(hi), "f"(lo));
    return d;
}
__device__ __forceinline__ uint tanh2(uint x) {
    uint y;
    asm("tanh.approx.f16x2 %0, %1;" : "=r"(y) : "r"(x));
    return y;
}
__device__ __forceinline__ uint hfma2(uint a, uint b, uint c) {
    uint d;
    asm("fma.rn.f16x2 %0, %1, %2, %3;" : "=r"(d) : "r"(a), "r"(b), "r"(c));
    return d;
}
__device__ __forceinline__ uint hmul2(uint a, uint b) {
    uint d;
    asm("mul.rn.f16x2 %0, %1, %2;" : "=r"(d) : "r"(a), "r"(b));
    return d;
}
#define H05 0x38003800u

// f16x2 LSTM cell pair straight from packed f16x2 gate registers
__device__ __forceinline__ uint cellpair2(uint di, uint dg, uint dq) {
    uint si = hfma2(tanh2(di), H05, H05);     // sigm(i)  (i pre-scaled 0.5)
    uint c  = hmul2(si, tanh2(dg));           // sigm(i)*tanh(g)
    uint so = hfma2(tanh2(dq), H05, H05);     // sigm(o)
    return hmul2(so, tanh2(c));               // h
}
// exact fp32 cell; ih = 0.5*i, oh = 0.5*o (weights pre-scaled)
__device__ __forceinline__ float cell_exact_h(float ih, float g, float oh) {
    float eg = __expf(-2.0f * fabsf(g));
    float ei = __expf(-2.0f * ih);
    float cc = copysignf(__fdividef(1.0f - eg, (1.0f + ei) * (1.0f + eg)), g);
    float ec = __expf(-2.0f * fabsf(cc));
    float eo = __expf(-2.0f * oh);
    return copysignf(__fdividef(1.0f - ec, (1.0f + eo) * (1.0f + ec)), cc);
}

// -------- frag coordinates: f2 = (T*3+g)*3+Kc ; u = f2*64 + lane*2 + r --------
// value(lane,r,e) = W[j = g*48 + T*8 + lane/4][k = Kc*16 + r*8 + (lane%4)*2 + e]
__global__ void prep_kernel(const float* __restrict__ w_ih,
                            const float* __restrict__ b_ih,
                            const float* __restrict__ b_hh)
{
    int l  = blockIdx.x >> 2;
    int u0 = (blockIdx.x & 3) * (UHALF / 4);
    for (int rem = u0 + threadIdx.x; rem < u0 + UHALF / 4; rem += blockDim.x) {
        int f2   = rem >> 6;
        int lane = (rem >> 1) & 31;
        int r    = rem & 1;
        int Kc = f2 % 3;
        int g  = (f2 / 3) % 3;
        int T  = f2 / 9;
        int m  = T * 8 + (lane >> 2);
        int k0 = Kc * 16 + r * 8 + (lane & 3) * 2;
        float v0 = 0.0f, v1 = 0.0f;
        if (m < EMB) {
            int rg = m + (g == 1 ? 86 : (g == 2 ? 129 : 0));   // i / g / o rows
            const float* wr = w_ih + ((size_t)l * 172 + rg) * EMB;
            float bias = b_ih[l * 172 + rg] + b_hh[l * 172 + rg];
            v0 = (k0 < EMB)     ? wr[k0]     : (k0 == EMB     ? bias : 0.0f);
            v1 = (k0 + 1 < EMB) ? wr[k0 + 1] : (k0 + 1 == EMB ? bias : 0.0f);
        }
        if (g != 1) { v0 *= 0.5f; v1 *= 0.5f; }    // fold sigm's x/2 into i,o
        g_Bh[(size_t)l * UHALF + rem] = pack_h2(v1, v0);
    }
}

// ---------------- f16 layer body (layers 0..61), f16 accumulator -------------
__device__ __forceinline__ void layer_f16(
    const char* __restrict__ bsm,
    const uint (&Ih)[3][4], uint (&Oh)[3][4], int lane)
{
    const int qq = lane & 3;
    #pragma unroll
    for (int T = 0; T < 6; T++) {
        uint dd[3][2];
        #pragma unroll
        for (int g = 0; g < 3; g++) { dd[g][0] = 0u; dd[g][1] = 0u; }
        #pragma unroll
        for (int g = 0; g < 3; g++)
            #pragma unroll
            for (int Kc = 0; Kc < 3; Kc++) {
                uint2 B = *(const uint2*)(bsm + (size_t)(((T*3+g)*3+Kc)) * 256 + lane * 8);
                mma_f16acc(dd[g], Ih[Kc], B.x, B.y);
            }
        uint p0 = cellpair2(dd[0][0], dd[1][0], dd[2][0]);   // row gr,   cols m0,m0+1
        uint p1 = cellpair2(dd[0][1], dd[1][1], dd[2][1]);   // row gr+8
        int m0 = T * 8 + 2 * qq;
        if (m0 + 1 == EMB) {               // k=43 "one" column (f16 1.0 hi half)
            p0 = (p0 & 0xFFFFu) | 0x3C000000u;
            p1 = (p1 & 0xFFFFu) | 0x3C000000u;
        }
        int Kc = T >> 1, hh = (T & 1) * 2;
        Oh[Kc][hh]     = p0;
        Oh[Kc][hh + 1] = p1;
    }
}

// ---------- tail layer body (f32 acc on f16 frags, exact cells) --------------
template<bool LAST>
__device__ __forceinline__ void layer_exact(
    const char* __restrict__ bsm,
    const uint (&Ih)[3][4], uint (&Oh)[3][4],
    int lane, int wp, float* hb)
{
    const int qq = lane & 3;
    const int gr = lane >> 2;
    #pragma unroll
    for (int T = 0; T < 6; T++) {
        float d[3][4];
        #pragma unroll
        for (int g = 0; g < 3; g++) {
            d[g][0] = 0.f; d[g][1] = 0.f; d[g][2] = 0.f; d[g][3] = 0.f;
        }
        #pragma unroll
        for (int g = 0; g < 3; g++)
            #pragma unroll
            for (int Kc = 0; Kc < 3; Kc++) {
                uint2 B = *(const uint2*)(bsm + (size_t)(((T*3+g)*3+Kc)) * 256 + lane * 8);
                mma_f16f32(d[g], Ih[Kc], B.x, B.y);
            }
        float h0 = cell_exact_h(d[0][0], d[1][0], d[2][0]);
        float h1 = cell_exact_h(d[0][1], d[1][1], d[2][1]);
        float h2 = cell_exact_h(d[0][2], d[1][2], d[2][2]);
        float h3 = cell_exact_h(d[0][3], d[1][3], d[2][3]);
        int m0 = T * 8 + 2 * qq;
        if (m0 + 1 == EMB) { h1 = 1.0f; h3 = 1.0f; }   // k=43 "one" column
        if (!LAST) {
            int Kc = T >> 1, hh = (T & 1) * 2;
            Oh[Kc][hh]     = pack_h2(h1, h0);
            Oh[Kc][hh + 1] = pack_h2(h3, h2);
        } else {
            int e0 = wp * 16 + gr;
            if (m0 < EMB) {
                hb[e0 * 45 + m0]       = h0;
                hb[(e0 + 8) * 45 + m0] = h2;
            }
            if (m0 + 1 < EMB) {
                hb[e0 * 45 + m0 + 1]       = h1;
                hb[(e0 + 8) * 45 + m0 + 1] = h3;
            }
        }
    }
}

__device__ __forceinline__ float fetch_emb(const float* emb, int e, int k) {
    if (k < EMB)  return emb[(size_t)e * EMB + k];
    if (k == EMB) return 1.0f;
    return 0.0f;
}
__device__ __forceinline__ void stage(uint sa, const uint* src, int t) {
    const char* g = reinterpret_cast<const char*>(src);
    #pragma unroll
    for (int i = 0; i < (HALF_B / 16 + TPB - 1) / TPB; i++) {
        int idx = t + i * TPB;
        if (idx < HALF_B / 16) cp16(sa + idx * 16, g + (size_t)idx * 16);
    }
    asm volatile("cp.async.commit_group;" ::: "memory");
}
#define STAGE_H16(sa, l) stage(sa, g_Bh + (size_t)(l) * UHALF, t)
#define CP_WAIT() asm volatile("cp.async.wait_group 0;" ::: "memory")

__global__ __launch_bounds__(TPB, 2)
void lstm_table_kernel(const float* __restrict__ emb,
                       const float* __restrict__ w_out,
                       const float* __restrict__ b_out)
{
    extern __shared__ char smem[];
    float* hb     = reinterpret_cast<float*>(smem + SM_HB);
    float* wout_s = reinterpret_cast<float*>(smem + SM_WOUT);
    float* bout_s = reinterpret_cast<float*>(smem + SM_BOUT);

    const int t = threadIdx.x;
    const int wp = t >> 5, lane = t & 31;
    const int gr = lane >> 2, qq = lane & 3;
    const int ebase = blockIdx.x * EPB;

    uint sa0 = smaddr(smem + SM_B0), sa1 = smaddr(smem + SM_B1);
    const char* buf0 = smem + SM_B0;
    const char* buf1 = smem + SM_B1;

    STAGE_H16(sa0, 0);                         // layer 0
    for (int i = t; i < OUT_DIM * EMB; i += TPB) wout_s[i] = w_out[i];
    if (t < OUT_DIM) bout_s[t] = b_out[t];

    // initial A fragments from embedding (f16), 1 etile per warp
    uint AhX[3][4], AhY[3][4];
    {
        int e0 = ebase + wp * 16 + gr;
        int ea = (e0 < VOCAB) ? e0 : VOCAB - 1;
        int eb = (e0 + 8 < VOCAB) ? e0 + 8 : VOCAB - 1;
        #pragma unroll
        for (int Kc = 0; Kc < 3; Kc++)
            #pragma unroll
            for (int hh = 0; hh < 2; hh++) {
                int k = Kc * 16 + hh * 8 + 2 * qq;
                AhX[Kc][hh * 2]     = pack_h2(fetch_emb(emb, ea, k + 1),
                                              fetch_emb(emb, ea, k));
                AhX[Kc][hh * 2 + 1] = pack_h2(fetch_emb(emb, eb, k + 1),
                                              fetch_emb(emb, eb, k));
            }
    }

    CP_WAIT();
    __syncthreads();

    // layers 0..61: f16 fast path (f16 accumulator, approx cells)
    #pragma unroll 1
    for (int l = 0; l < 62; l += 2) {
        STAGE_H16(sa1, l + 1);
        layer_f16(buf0, AhX, AhY, lane);
        CP_WAIT(); __syncthreads();
        STAGE_H16(sa0, l + 2);                 // l+2 <= 62
        layer_f16(buf1, AhY, AhX, lane);
        CP_WAIT(); __syncthreads();
    }
    // buf0 now holds layer 62 frags
    STAGE_H16(sa1, 63);
    layer_exact<false>(buf0, AhX, AhY, lane, wp, hb);   // layer 62: f32 acc, exact
    CP_WAIT(); __syncthreads();
    layer_exact<true>(buf1, AhY, AhX, lane, wp, hb);    // layer 63 -> hb
    __syncthreads();

    // ---- head: logits + log_softmax -> g_table ----
    if (t < EPB && ebase + t < VOCAB) {
        float lg[OUT_DIM];
        #pragma unroll
        for (int j = 0; j < OUT_DIM; j++) {
            float a = bout_s[j];
            #pragma unroll
            for (int k = 0; k < EMB; k++)
                a = fmaf(wout_s[j * EMB + k], hb[t * 45 + k], a);
            lg[j] = a;
        }
        float mx = lg[0];
        #pragma unroll
        for (int j = 1; j < OUT_DIM; j++) mx = fmaxf(mx, lg[j]);
        float s = 0.0f;
        #pragma unroll
        for (int j = 0; j < OUT_DIM; j++) s += __expf(lg[j] - mx);
        float lse = mx + __logf(s);
        #pragma unroll
        for (int j = 0; j < OUT_DIM; j++)
            g_table[(size_t)(ebase + t) * OUT_DIM + j] = lg[j] - lse;
    }
}

// ---------------- gather: single launch, streaming stores ----------------
__global__ void gather4_kernel(const int* __restrict__ tokens,
                               float4* __restrict__ out4, int n4)
{
    int i = blockIdx.x * blockDim.x + threadIdx.x;
    if (i >= n4) return;
    int base = i * 4;
    float r[4];
    #pragma unroll
    for (int u = 0; u < 4; u++) {
        int idx = base + u;
        int n = idx / OUT_DIM;
        int j = idx - n * OUT_DIM;
        r[u] = __ldg(&g_table[__ldg(&tokens[n]) * OUT_DIM + j]);
    }
    float4 v = make_float4(r[0], r[1], r[2], r[3]);
    asm volatile("st.global.cs.v4.f32 [%0], {%1,%2,%3,%4};"
                 :: "l"(out4 + i), "f"(v.x), "f"(v.y), "f"(v.z), "f"(v.w)
                 : "memory");
}

extern "C" void kernel_launch(void* const* d_in, const int* in_sizes, int n_in,
                              void* d_out, int out_size)
{
    const int*   tokens = (const int*)  d_in[0];
    const float* emb    = (const float*)d_in[1];
    const float* w_ih   = (const float*)d_in[2];
    // d_in[3] = w_hh : unused (h_prev = 0)
    const float* b_ih   = (const float*)d_in[4];
    const float* b_hh   = (const float*)d_in[5];
    const float* w_out  = (const float*)d_in[6];
    const float* b_out  = (const float*)d_in[7];
    float* out = (float*)d_out;

    prep_kernel<<<256, 256>>>(w_ih, b_ih, b_hh);

    cudaFuncSetAttribute(lstm_table_kernel,
                         cudaFuncAttributeMaxDynamicSharedMemorySize, SM_TOTAL);
    lstm_table_kernel<<<NBLK, TPB, SM_TOTAL>>>(emb, w_out, b_out);

    int n4 = out_size / 4;
    gather4_kernel<<<(n4 + 255) / 256, 256>>>(tokens, (float4*)out, n4);
}